// round 3
// baseline (speedup 1.0000x reference)
#include <cuda_runtime.h>
#include <cuda_bf16.h>

#define NUM_EXPERTS 16
#define Z_LOSS 1e-3f
#define ALPHA (1.0f / 1000.0f)

#define R_BLOCKS 2048
#define R_THREADS 256
// total elements = 4*4096*2048 = 33554432 floats = 8388608 float4
// 8388608 / (2048*256) = 16 float4 per thread exactly

__device__ float g_partials[R_BLOCKS];
__device__ int g_ticket = 0;   // reset to 0 by the last block each launch

__global__ __launch_bounds__(R_THREADS) void router_kernel(
    const float4* __restrict__ x,
    const float* __restrict__ prototypes,
    const float* __restrict__ usage_ema,
    float* __restrict__ out, int out_size, float inv_n)
{
    __shared__ float sdata[R_THREADS / 32];
    __shared__ double ddata[R_THREADS / 32];
    __shared__ bool is_last;
    const int tid = threadIdx.x;

    // ---- phase 1: grid-strided coalesced partial sum (16 independent LDG.128) ----
    const unsigned gid = blockIdx.x * R_THREADS + tid;
    const unsigned stride = R_BLOCKS * R_THREADS;

    float s0 = 0.f, s1 = 0.f, s2 = 0.f, s3 = 0.f;
#pragma unroll
    for (int i = 0; i < 16; i++) {
        float4 v = x[gid + (unsigned)i * stride];
        s0 += v.x; s1 += v.y; s2 += v.z; s3 += v.w;
    }
    float s = (s0 + s1) + (s2 + s3);

#pragma unroll
    for (int off = 16; off > 0; off >>= 1)
        s += __shfl_down_sync(0xffffffffu, s, off);

    if ((tid & 31) == 0) sdata[tid >> 5] = s;
    __syncthreads();
    if (tid < 32) {
        float v = (tid < R_THREADS / 32) ? sdata[tid] : 0.f;
#pragma unroll
        for (int off = 4; off > 0; off >>= 1)
            v += __shfl_down_sync(0xffffffffu, v, off);
        if (tid == 0) {
            g_partials[blockIdx.x] = v;
            __threadfence();
            int old = atomicAdd(&g_ticket, 1);
            is_last = (old == R_BLOCKS - 1);
        }
    }
    __syncthreads();
    if (!is_last) return;

    // ---- phase 2 (last block only): reduce partials in double ----
    double d = 0.0;
#pragma unroll
    for (int i = 0; i < R_BLOCKS / R_THREADS; i++)
        d += (double)__ldcg(&g_partials[tid + i * R_THREADS]);
#pragma unroll
    for (int off = 16; off > 0; off >>= 1)
        d += __shfl_down_sync(0xffffffffu, d, off);
    if ((tid & 31) == 0) ddata[tid >> 5] = d;

    // initialize every output element (d_out is poisoned with 0xAA)
    for (int i = tid; i < out_size; i += R_THREADS) out[i] = 0.0f;
    __syncthreads();

    if (tid == 0) {
        double tot = 0.0;
#pragma unroll
        for (int i = 0; i < R_THREADS / 32; i++) tot += ddata[i];
        float xm = (float)(tot * (double)inv_n);

        // sim = -(p_e - x)^2 ; softmax
        float sim[NUM_EXPERTS];
        float mx = -3.4e38f;
#pragma unroll
        for (int e = 0; e < NUM_EXPERTS; e++) {
            float dd = prototypes[e] - xm;
            sim[e] = -dd * dd;
            if (sim[e] > mx) mx = sim[e];
        }
        float probs[NUM_EXPERTS];
        float denom = 0.f;
#pragma unroll
        for (int e = 0; e < NUM_EXPERTS; e++) {
            probs[e] = expf(sim[e] - mx);
            denom += probs[e];
        }
        float inv_denom = 1.0f / denom;
#pragma unroll
        for (int e = 0; e < NUM_EXPERTS; e++) probs[e] *= inv_denom;

        // stable top-2 (ties -> lowest index, matching jax.lax.top_k)
        int i0 = 0;
        for (int e = 1; e < NUM_EXPERTS; e++)
            if (probs[e] > probs[i0]) i0 = e;
        int i1 = (i0 == 0) ? 1 : 0;
        for (int e = 0; e < NUM_EXPERTS; e++) {
            if (e == i0) continue;
            if (probs[e] > probs[i1]) i1 = e;
        }

        float mask[NUM_EXPERTS];
#pragma unroll
        for (int e = 0; e < NUM_EXPERTS; e++) mask[e] = 0.f;
        mask[i0] = 1.f; mask[i1] = 1.f;

        const float target = 1.0f / NUM_EXPERTS;
        float acc = 0.f;
        float ema[NUM_EXPERTS];
#pragma unroll
        for (int e = 0; e < NUM_EXPERTS; e++) {
            ema[e] = (1.0f - ALPHA) * usage_ema[e] + ALPHA * mask[e];
            float dd = ema[e] - target;
            acc += dd * dd;
        }
        float balance_loss = (acc / NUM_EXPERTS) * Z_LOSS;

        // output layout: mask[16], probs[16], loss[1], ema[16], topk_idx[2]
        int o = 0;
#pragma unroll
        for (int e = 0; e < NUM_EXPERTS; e++) out[o++] = mask[e];
#pragma unroll
        for (int e = 0; e < NUM_EXPERTS; e++) out[o++] = probs[e];
        out[o++] = balance_loss;
#pragma unroll
        for (int e = 0; e < NUM_EXPERTS; e++) out[o++] = ema[e];
        out[o++] = (float)i0;
        out[o++] = (float)i1;

        // reset ticket for the next graph replay
        g_ticket = 0;
    }
}

extern "C" void kernel_launch(void* const* d_in, const int* in_sizes, int n_in,
                              void* d_out, int out_size) {
    const float* wm        = (const float*)d_in[0];
    const float* protos    = (const float*)d_in[1];
    const float* usage_ema = (const float*)d_in[2];
    float* out = (float*)d_out;

    const int n = in_sizes[0];  // 33554432
    router_kernel<<<R_BLOCKS, R_THREADS>>>((const float4*)wm, protos, usage_ema,
                                           out, out_size, 1.0f / (float)n);
}

// round 6
// speedup vs baseline: 1.1414x; 1.1414x over previous
#include <cuda_runtime.h>
#include <cuda_bf16.h>

#define NUM_EXPERTS 16
#define Z_LOSS 1e-3f
#define ALPHA (1.0f / 1000.0f)

#define R_BLOCKS 2048
#define R_THREADS 256
// total elements = 4*4096*2048 = 33554432 floats = 8388608 float4
// 8388608 / (2048*256) = 16 float4 per thread exactly

__device__ float g_partials[R_BLOCKS];
__device__ int g_ticket = 0;   // reset to 0 by the last block each launch

__global__ __launch_bounds__(R_THREADS, 8) void router_kernel(
    const float4* __restrict__ x,
    const float* __restrict__ prototypes,
    const float* __restrict__ usage_ema,
    float* __restrict__ out, int out_size, float inv_n)
{
    __shared__ float sdata[R_THREADS / 32];
    __shared__ bool is_last;
    const int tid = threadIdx.x;

    // ---- phase 1: grid-strided coalesced partial sum ----
    const unsigned gid = blockIdx.x * R_THREADS + tid;
    const unsigned stride = R_BLOCKS * R_THREADS;

    float s0 = 0.f, s1 = 0.f, s2 = 0.f, s3 = 0.f;
#pragma unroll
    for (int i = 0; i < 16; i++) {
        float4 v = x[gid + (unsigned)i * stride];
        s0 += v.x; s1 += v.y; s2 += v.z; s3 += v.w;
    }
    float s = (s0 + s1) + (s2 + s3);

#pragma unroll
    for (int off = 16; off > 0; off >>= 1)
        s += __shfl_down_sync(0xffffffffu, s, off);

    if ((tid & 31) == 0) sdata[tid >> 5] = s;
    __syncthreads();
    if (tid < 32) {
        float v = (tid < R_THREADS / 32) ? sdata[tid] : 0.f;
#pragma unroll
        for (int off = 4; off > 0; off >>= 1)
            v += __shfl_down_sync(0xffffffffu, v, off);
        if (tid == 0) {
            g_partials[blockIdx.x] = v;
            __threadfence();
            int old = atomicAdd(&g_ticket, 1);
            is_last = (old == R_BLOCKS - 1);
        }
    }
    __syncthreads();
    if (!is_last) return;

    // ---- phase 2 (last block only): reduce partials in float ----
    float t = 0.f;
#pragma unroll
    for (int i = 0; i < R_BLOCKS / R_THREADS; i++)
        t += __ldcg(&g_partials[tid + i * R_THREADS]);
#pragma unroll
    for (int off = 16; off > 0; off >>= 1)
        t += __shfl_down_sync(0xffffffffu, t, off);
    if ((tid & 31) == 0) sdata[tid >> 5] = t;

    // initialize every output element (d_out is poisoned with 0xAA)
    for (int i = tid; i < out_size; i += R_THREADS) out[i] = 0.0f;
    __syncthreads();

    if (tid == 0) {
        float tot = 0.f;
#pragma unroll
        for (int i = 0; i < R_THREADS / 32; i++) tot += sdata[i];
        float xm = tot * inv_n;

        // sim = -(p_e - x)^2 ; softmax
        float sim[NUM_EXPERTS];
        float mx = -3.4e38f;
#pragma unroll
        for (int e = 0; e < NUM_EXPERTS; e++) {
            float dd = prototypes[e] - xm;
            sim[e] = -dd * dd;
            if (sim[e] > mx) mx = sim[e];
        }
        float probs[NUM_EXPERTS];
        float denom = 0.f;
#pragma unroll
        for (int e = 0; e < NUM_EXPERTS; e++) {
            probs[e] = expf(sim[e] - mx);
            denom += probs[e];
        }
        float inv_denom = 1.0f / denom;
#pragma unroll
        for (int e = 0; e < NUM_EXPERTS; e++) probs[e] *= inv_denom;

        // stable top-2 (ties -> lowest index, matching jax.lax.top_k)
        int i0 = 0;
        for (int e = 1; e < NUM_EXPERTS; e++)
            if (probs[e] > probs[i0]) i0 = e;
        int i1 = (i0 == 0) ? 1 : 0;
        for (int e = 0; e < NUM_EXPERTS; e++) {
            if (e == i0) continue;
            if (probs[e] > probs[i1]) i1 = e;
        }

        float mask[NUM_EXPERTS];
#pragma unroll
        for (int e = 0; e < NUM_EXPERTS; e++) mask[e] = 0.f;
        mask[i0] = 1.f; mask[i1] = 1.f;

        const float target = 1.0f / NUM_EXPERTS;
        float acc = 0.f;
        float ema[NUM_EXPERTS];
#pragma unroll
        for (int e = 0; e < NUM_EXPERTS; e++) {
            ema[e] = (1.0f - ALPHA) * usage_ema[e] + ALPHA * mask[e];
            float dd = ema[e] - target;
            acc += dd * dd;
        }
        float balance_loss = (acc / NUM_EXPERTS) * Z_LOSS;

        // output layout: mask[16], probs[16], loss[1], ema[16], topk_idx[2]
        int o = 0;
#pragma unroll
        for (int e = 0; e < NUM_EXPERTS; e++) out[o++] = mask[e];
#pragma unroll
        for (int e = 0; e < NUM_EXPERTS; e++) out[o++] = probs[e];
        out[o++] = balance_loss;
#pragma unroll
        for (int e = 0; e < NUM_EXPERTS; e++) out[o++] = ema[e];
        out[o++] = (float)i0;
        out[o++] = (float)i1;

        // reset ticket for the next graph replay
        g_ticket = 0;
    }
}

extern "C" void kernel_launch(void* const* d_in, const int* in_sizes, int n_in,
                              void* d_out, int out_size) {
    const float* wm        = (const float*)d_in[0];
    const float* protos    = (const float*)d_in[1];
    const float* usage_ema = (const float*)d_in[2];
    float* out = (float*)d_out;

    const int n = in_sizes[0];  // 33554432
    router_kernel<<<R_BLOCKS, R_THREADS>>>((const float4*)wm, protos, usage_ema,
                                           out, out_size, 1.0f / (float)n);
}

// round 7
// speedup vs baseline: 1.2102x; 1.0602x over previous
#include <cuda_runtime.h>
#include <cuda_bf16.h>

#define NUM_EXPERTS 16
#define Z_LOSS 1e-3f
#define ALPHA (1.0f / 1000.0f)

#define R_BLOCKS 1184            // 148 SMs * 8 blocks -> exactly one wave
#define R_THREADS 256
#define N4_TOTAL 8388608u        // 4*4096*2048 floats / 4
#define R_STRIDE (R_BLOCKS * R_THREADS)   // 303104
#define FULL_ITERS 27u           // 27*303104 = 8183808 <= N4, remainder 204800 predicated

__device__ float g_partials[R_BLOCKS];
__device__ int g_ticket = 0;   // reset to 0 by the last block each launch

__global__ __launch_bounds__(R_THREADS, 8) void router_kernel(
    const float4* __restrict__ x,
    const float* __restrict__ prototypes,
    const float* __restrict__ usage_ema,
    float* __restrict__ out, int out_size, float inv_n)
{
    __shared__ float sdata[R_THREADS / 32];
    __shared__ bool is_last;
    const int tid = threadIdx.x;

    // ---- phase 1: single-wave, perfectly balanced coalesced stream ----
    const unsigned gid = blockIdx.x * R_THREADS + tid;

    float s0 = 0.f, s1 = 0.f, s2 = 0.f, s3 = 0.f;
#pragma unroll
    for (unsigned i = 0; i < FULL_ITERS; i++) {
        float4 v = __ldcs(&x[gid + i * R_STRIDE]);
        s0 += v.x; s1 += v.y; s2 += v.z; s3 += v.w;
    }
    {
        unsigned idx = gid + FULL_ITERS * R_STRIDE;
        if (idx < N4_TOTAL) {
            float4 v = __ldcs(&x[idx]);
            s0 += v.x; s1 += v.y; s2 += v.z; s3 += v.w;
        }
    }
    float s = (s0 + s1) + (s2 + s3);

#pragma unroll
    for (int off = 16; off > 0; off >>= 1)
        s += __shfl_down_sync(0xffffffffu, s, off);

    if ((tid & 31) == 0) sdata[tid >> 5] = s;
    __syncthreads();
    if (tid < 32) {
        float v = (tid < R_THREADS / 32) ? sdata[tid] : 0.f;
#pragma unroll
        for (int off = 4; off > 0; off >>= 1)
            v += __shfl_down_sync(0xffffffffu, v, off);
        if (tid == 0) {
            g_partials[blockIdx.x] = v;
            __threadfence();
            int old = atomicAdd(&g_ticket, 1);
            is_last = (old == R_BLOCKS - 1);
        }
    }
    __syncthreads();
    if (!is_last) return;

    // ---- phase 2 (last block only): reduce 1184 partials ----
    float t = 0.f;
#pragma unroll
    for (int i = 0; i < (R_BLOCKS + R_THREADS - 1) / R_THREADS; i++) {
        int idx = tid + i * R_THREADS;
        if (idx < R_BLOCKS) t += __ldcg(&g_partials[idx]);
    }
#pragma unroll
    for (int off = 16; off > 0; off >>= 1)
        t += __shfl_down_sync(0xffffffffu, t, off);
    if ((tid & 31) == 0) sdata[tid >> 5] = t;

    // initialize every output element (d_out is poisoned with 0xAA)
    for (int i = tid; i < out_size; i += R_THREADS) out[i] = 0.0f;
    __syncthreads();

    if (tid == 0) {
        float tot = 0.f;
#pragma unroll
        for (int i = 0; i < R_THREADS / 32; i++) tot += sdata[i];
        float xm = tot * inv_n;

        // sim = -(p_e - x)^2 ; softmax
        float sim[NUM_EXPERTS];
        float mx = -3.4e38f;
#pragma unroll
        for (int e = 0; e < NUM_EXPERTS; e++) {
            float dd = prototypes[e] - xm;
            sim[e] = -dd * dd;
            if (sim[e] > mx) mx = sim[e];
        }
        float probs[NUM_EXPERTS];
        float denom = 0.f;
#pragma unroll
        for (int e = 0; e < NUM_EXPERTS; e++) {
            probs[e] = expf(sim[e] - mx);
            denom += probs[e];
        }
        float inv_denom = 1.0f / denom;
#pragma unroll
        for (int e = 0; e < NUM_EXPERTS; e++) probs[e] *= inv_denom;

        // stable top-2 (ties -> lowest index, matching jax.lax.top_k)
        int i0 = 0;
        for (int e = 1; e < NUM_EXPERTS; e++)
            if (probs[e] > probs[i0]) i0 = e;
        int i1 = (i0 == 0) ? 1 : 0;
        for (int e = 0; e < NUM_EXPERTS; e++) {
            if (e == i0) continue;
            if (probs[e] > probs[i1]) i1 = e;
        }

        float mask[NUM_EXPERTS];
#pragma unroll
        for (int e = 0; e < NUM_EXPERTS; e++) mask[e] = 0.f;
        mask[i0] = 1.f; mask[i1] = 1.f;

        const float target = 1.0f / NUM_EXPERTS;
        float acc = 0.f;
        float ema[NUM_EXPERTS];
#pragma unroll
        for (int e = 0; e < NUM_EXPERTS; e++) {
            ema[e] = (1.0f - ALPHA) * usage_ema[e] + ALPHA * mask[e];
            float dd = ema[e] - target;
            acc += dd * dd;
        }
        float balance_loss = (acc / NUM_EXPERTS) * Z_LOSS;

        // output layout: mask[16], probs[16], loss[1], ema[16], topk_idx[2]
        int o = 0;
#pragma unroll
        for (int e = 0; e < NUM_EXPERTS; e++) out[o++] = mask[e];
#pragma unroll
        for (int e = 0; e < NUM_EXPERTS; e++) out[o++] = probs[e];
        out[o++] = balance_loss;
#pragma unroll
        for (int e = 0; e < NUM_EXPERTS; e++) out[o++] = ema[e];
        out[o++] = (float)i0;
        out[o++] = (float)i1;

        // reset ticket for the next graph replay
        g_ticket = 0;
    }
}

extern "C" void kernel_launch(void* const* d_in, const int* in_sizes, int n_in,
                              void* d_out, int out_size) {
    const float* wm        = (const float*)d_in[0];
    const float* protos    = (const float*)d_in[1];
    const float* usage_ema = (const float*)d_in[2];
    float* out = (float*)d_out;

    const int n = in_sizes[0];  // 33554432
    router_kernel<<<R_BLOCKS, R_THREADS>>>((const float4*)wm, protos, usage_ema,
                                           out, out_size, 1.0f / (float)n);
}